// round 12
// baseline (speedup 1.0000x reference)
#include <cuda_runtime.h>
#include <cuda_fp16.h>
#include <cstdint>

// Problem constants
#define B_    16
#define D_    256
#define S_    1024
#define NTOK  16384
#define KC    8192
#define BDS   4194304
#define NGRP  1024                // KC/8 code-groups of 8

#define MB_TOT (NTOK / 16)        // 1024 token blocks of 16
#define KS_TOT (D_ / 16)          // 16 k-steps of 16

// Main kernel tiling (8 warps, 4m x 4n warp microtiles), hi-only MMA
#define MT     128
#define NT     128
#define NPARTS 8
#define NITERL 64                 // 8 tiles x 8 kspairs

// smem: A hi tile + gmin staging
#define SMEM_A_BYTES 65536        // [8 mb][16 ks][32 lane][4] u32
#define SMEM_GM      8192         // [128][16] floats
#define SMEM_MAIN (SMEM_A_BYTES + SMEM_GM)

// Device scratch (allocations forbidden)
__device__ uint32_t g_Ah[MB_TOT * KS_TOT * 32 * 4];   // 8 MB hi A-fragments
__device__ uint32_t g_B [NGRP * 8 * 32 * 4];          // 4 MB hi B-fragments
__device__ float    g_ET[KC * D_];                    // 8 MB code-major E (fp32)
__device__ float    g_csq[KC];
__device__ float    g_gmin[(size_t)NTOK * NGRP];      // 64 MB group minima
__device__ int      g_ind[NTOK];

// ---------------------------- helpers --------------------------------------
__device__ __forceinline__ uint32_t smem_u32(const void* p) {
    uint32_t a;
    asm("{ .reg .u64 t; cvta.to.shared.u64 t, %1; cvt.u32.u64 %0, t; }" : "=r"(a) : "l"(p));
    return a;
}
__device__ __forceinline__ void cpasync16(uint32_t dst, const void* src) {
    asm volatile("cp.async.cg.shared.global [%0], [%1], 16;" :: "r"(dst), "l"(src));
}
__device__ __forceinline__ void mma16816(float* c, const uint32_t* a, const uint32_t* b) {
    asm volatile("mma.sync.aligned.m16n8k16.row.col.f32.f16.f16.f32 "
                 "{%0,%1,%2,%3}, {%4,%5,%6,%7}, {%8,%9}, {%0,%1,%2,%3};"
                 : "+f"(c[0]), "+f"(c[1]), "+f"(c[2]), "+f"(c[3])
                 : "r"(a[0]), "r"(a[1]), "r"(a[2]), "r"(a[3]), "r"(b[0]), "r"(b[1]));
}
__device__ __forceinline__ uint32_t pack_h2(__half lo, __half hi) {
    __half2 h = __halves2half2(lo, hi);
    return *reinterpret_cast<uint32_t*>(&h);
}

// ---------------------------------------------------------------------------
// Fused preprocessing. Blocks [0, MB_TOT): x -> hi A-fragments.
// Blocks [MB_TOT, +KC/32): E -> hi B-fragments + csq + code-major E_T.
// ---------------------------------------------------------------------------
__global__ void vq_split_xe(const float* __restrict__ x,
                            const float* __restrict__ E) {
    __shared__ char sm[36000];
    const int tid = threadIdx.x;

    if (blockIdx.x < MB_TOT) {
        float* xs = (float*)sm;                  // [d][tok] 16 KB
        const int mb = blockIdx.x;
        const int t0 = mb * 16;
        const int b  = t0 >> 10;
        const int s0 = t0 & (S_ - 1);

        for (int i = tid; i < D_ * 16; i += 256) {
            int d = i >> 4, tok = i & 15;
            xs[d * 16 + tok] = x[((size_t)b * D_ + d) * S_ + s0 + tok];
        }
        __syncthreads();

        const size_t obase = (size_t)mb * (KS_TOT * 32 * 4);
        for (int oi = tid; oi < KS_TOT * 32 * 4; oi += 256) {
            int ks = oi >> 7, rem = oi & 127;
            int lane = rem >> 2, r = rem & 3;
            int gid = lane >> 2, tig = lane & 3;
            int row = gid + (r & 1) * 8;
            int c0  = ks * 16 + tig * 2 + (r >> 1) * 8;
            float v0 = xs[c0 * 16 + row];
            float v1 = xs[(c0 + 1) * 16 + row];
            g_Ah[obase + oi] = pack_h2(__float2half_rn(v0), __float2half_rn(v1));
        }
    } else {
        float* es   = (float*)sm;                // [256][33] padded, 33.8 KB
        float* cred = (float*)(sm + 33792);      // [8][32]
        const int eb = blockIdx.x - MB_TOT;
        const int k0 = eb * 32;

        for (int i = tid; i < D_ * 32; i += 256) {
            int d = i >> 5, kk = i & 31;
            es[d * 33 + kk] = E[(size_t)d * KC + k0 + kk];
        }
        __syncthreads();

        {   // csq: deterministic part-ordered sum of squares per code column.
            const int kk = tid & 31, part = tid >> 5;
            float s = 0.f;
#pragma unroll 8
            for (int dd = 0; dd < 32; ++dd) {
                float v = es[(part * 32 + dd) * 33 + kk];
                s = fmaf(v, v, s);
            }
            cred[part * 32 + kk] = s;
        }
        __syncthreads();
        if (tid < 32) {
            float s = cred[tid];
#pragma unroll
            for (int p = 1; p < 8; ++p) s += cred[p * 32 + tid];
            g_csq[k0 + tid] = s;
        }

        // Code-major fp32 copy E_T[k][d] (for the exact verification pass).
        for (int i = tid; i < 2048; i += 256) {
            int kl = i >> 6, d4 = (i & 63) * 4;
            float4 v;
            v.x = es[(d4 + 0) * 33 + kl];
            v.y = es[(d4 + 1) * 33 + kl];
            v.z = es[(d4 + 2) * 33 + kl];
            v.w = es[(d4 + 3) * 33 + kl];
            *(float4*)&g_ET[(size_t)(k0 + kl) * D_ + d4] = v;
        }

        // Hi B-fragments: [nb][kspair][lane] uint4 = {ks0r0, ks0r1, ks1r0, ks1r1}.
        for (int fi = tid; fi < 1024; fi += 256) {
            int nbl    = fi >> 8;                // 0..3
            int kspair = (fi >> 5) & 7;
            int lane   = fi & 31;
            int gid = lane >> 2, tig = lane & 3;
            int kl  = nbl * 8 + gid;
            uint32_t frag[4];
#pragma unroll
            for (int ksl = 0; ksl < 2; ++ksl)
#pragma unroll
                for (int r = 0; r < 2; ++r) {
                    int d0 = (kspair * 2 + ksl) * 16 + tig * 2 + r * 8;
                    frag[ksl * 2 + r] = pack_h2(__float2half_rn(es[d0 * 33 + kl]),
                                                __float2half_rn(es[(d0 + 1) * 33 + kl]));
                }
            *(uint4*)&g_B[(((size_t)(eb * 4 + nbl) * 8 + kspair) * 32 + lane) * 4] =
                *(uint4*)frag;
        }
    }
}

// ---------------------------------------------------------------------------
// Pass 1: hi*hi MMA only; per-(token, 8-code-group) approx minima to g_gmin.
// ---------------------------------------------------------------------------
__device__ __forceinline__ void loadB(uint4* bnew, int it, int nwarp, int lane) {
    const int ntile = it >> 3, kspair = it & 7;
    const uint4* base = (const uint4*)g_B +
        (((size_t)(ntile * 16 + nwarp * 4) * 8 + kspair) * 32 + lane);
#pragma unroll
    for (int nf = 0; nf < 4; ++nf)
        bnew[nf] = __ldg(base + nf * 256);       // nf stride: 8*32 uint4
}

#define MMA_ITER(II)                                                          \
    do {                                                                      \
        const int it = it0 + (II);                                            \
        const int ntile = it >> 3, kspair = it & 7;                           \
        uint4 bcur[4];                                                        \
        _Pragma("unroll")                                                     \
        for (int q = 0; q < 4; ++q) bcur[q] = bnxt[q];                        \
        if ((II) + 1 < NITERL) loadB(bnxt, it + 1, nwarp, lane);              \
        if (kspair == 0) {                                                    \
            _Pragma("unroll")                                                 \
            for (int mf = 0; mf < 4; ++mf)                                    \
                _Pragma("unroll")                                             \
                for (int nf = 0; nf < 4; ++nf)                                \
                    _Pragma("unroll")                                         \
                    for (int c = 0; c < 4; ++c) acc[mf][nf][c] = 0.f;         \
            _Pragma("unroll")                                                 \
            for (int nf = 0; nf < 4; ++nf) {                                  \
                int kq = ntile * NT + (nwarp * 4 + nf) * 8 + tig * 2;         \
                cregs[nf][0] = __ldg(&g_csq[kq]);                             \
                cregs[nf][1] = __ldg(&g_csq[kq + 1]);                         \
            }                                                                 \
        }                                                                     \
        _Pragma("unroll")                                                     \
        for (int ksl = 0; ksl < 2; ++ksl) {                                   \
            const int ks = kspair * 2 + ksl;                                  \
            uint32_t ah[4][4];                                                \
            _Pragma("unroll")                                                 \
            for (int mf = 0; mf < 4; ++mf)                                    \
                *(uint4*)ah[mf] =                                             \
                    *(const uint4*)(As + (((mwarp * 4 + mf) * 16 + ks) * 32 + lane) * 4); \
            _Pragma("unroll")                                                 \
            for (int mf = 0; mf < 4; ++mf)                                    \
                _Pragma("unroll")                                             \
                for (int nf = 0; nf < 4; ++nf)                                \
                    mma16816(acc[mf][nf], ah[mf],                             \
                             ((const uint32_t*)&bcur[nf]) + ksl * 2);         \
        }                                                                     \
        if (kspair == 7) {                                                    \
            _Pragma("unroll")                                                 \
            for (int mf = 0; mf < 4; ++mf)                                    \
                _Pragma("unroll")                                             \
                for (int hh = 0; hh < 2; ++hh)                                \
                    _Pragma("unroll")                                         \
                    for (int nf = 0; nf < 4; ++nf) {                          \
                        float m0 = fmaf(-2.f, acc[mf][nf][hh * 2],     cregs[nf][0]); \
                        float m1 = fmaf(-2.f, acc[mf][nf][hh * 2 + 1], cregs[nf][1]); \
                        float gm = fminf(m0, m1);                             \
                        gm = fminf(gm, __shfl_xor_sync(0xffffffffu, gm, 1));  \
                        gm = fminf(gm, __shfl_xor_sync(0xffffffffu, gm, 2));  \
                        if (tig == 0)                                         \
                            sgm[(mwarp * 64 + mf * 16 + hh * 8 + gid) * 16 +  \
                                nwarp * 4 + nf] = gm;                         \
                    }                                                         \
            __syncthreads();                                                  \
            {                                                                 \
                int r = tid >> 1, c0 = (tid & 1) * 8;                         \
                float4 va = *(float4*)&sgm[r * 16 + c0];                      \
                float4 vb = *(float4*)&sgm[r * 16 + c0 + 4];                  \
                float* dst = &g_gmin[(size_t)(n0 + r) * NGRP + ntile * 16 + c0]; \
                *(float4*)dst = va;                                           \
                *(float4*)(dst + 4) = vb;                                     \
            }                                                                 \
            __syncthreads();                                                  \
        }                                                                     \
    } while (0)

__global__ __launch_bounds__(256, 1) void vq_mma_kernel() {
    extern __shared__ char smem[];
    uint32_t* As = (uint32_t*)smem;
    float* sgm = (float*)(smem + SMEM_A_BYTES);
    const uint32_t sA = smem_u32(As);

    const int tid = threadIdx.x;
    const int wid = tid >> 5, lane = tid & 31;
    const int gid = lane >> 2, tig = lane & 3;
    const int mwarp = wid >> 2, nwarp = wid & 3;

    const int bx = blockIdx.x;                // 0..1023
    const int part   = bx & (NPARTS - 1);
    const int tileid = bx >> 3;
    const int mb0 = tileid * 8;
    const int n0  = tileid * MT;
    const int it0 = part * NITERL;

    // B pipeline head first (LDGs in flight during the A prologue).
    uint4 bnxt[4];
    loadB(bnxt, it0, nwarp, lane);

    // A prologue (hi only, 64 KB) in two commit groups: ks 0-7, ks 8-15.
    {
        const uint32_t* srcH = g_Ah + (size_t)mb0 * (KS_TOT * 32 * 4);
#pragma unroll
        for (int half = 0; half < 2; ++half) {
            for (int u = tid; u < 2048; u += 256) {
                int mb = u >> 8, ks = ((u >> 5) & 7) + half * 8, ln = u & 31;
                int unit = (mb * 16 + ks) * 32 + ln;     // 16-byte units
                cpasync16(sA + unit * 16, srcH + unit * 4);
            }
            asm volatile("cp.async.commit_group;" ::: "memory");
        }
    }

    float acc[4][4][4];
    float cregs[4][2];

    asm volatile("cp.async.wait_group 1;" ::: "memory");
    __syncthreads();
#pragma unroll 1
    for (int ii = 0; ii < 4; ++ii) MMA_ITER(ii);

    asm volatile("cp.async.wait_group 0;" ::: "memory");
    __syncthreads();
#pragma unroll 1
    for (int ii = 4; ii < NITERL; ++ii) MMA_ITER(ii);
}

// ---------------------------------------------------------------------------
// Pass 2: exact fp32 verification. One warp per token.
// thresh = min(gmin) + 2(||xh||*Mel + ||x-xh||*Me) + eps; exact-scan all
// qualifying 8-code groups in ascending k; lowest index wins ties.
// ---------------------------------------------------------------------------
__global__ __launch_bounds__(256, 1) void vq_finalize(const float* __restrict__ x) {
    const int tid = threadIdx.x;
    const int wid = tid >> 5, lane = tid & 31;
    const int n = blockIdx.x * 8 + wid;
    const int b = n >> 10, s = n & (S_ - 1);

    float xv[8];
    const float* xb = x + ((size_t)b * D_) * S_ + s;
#pragma unroll
    for (int j = 0; j < 8; ++j) xv[j] = __ldg(&xb[(size_t)(lane + j * 32) * S_]);

    // Actual hi/residual norms (same rounding as the fragments).
    float s1 = 0.f, s2 = 0.f;
#pragma unroll
    for (int j = 0; j < 8; ++j) {
        float h = __half2float(__float2half_rn(xv[j]));
        float r = xv[j] - h;
        s1 = fmaf(h, h, s1);
        s2 = fmaf(r, r, s2);
    }
#pragma unroll
    for (int off = 16; off; off >>= 1) {
        s1 += __shfl_xor_sync(0xffffffffu, s1, off);
        s2 += __shfl_xor_sync(0xffffffffu, s2, off);
    }
    // Mel = 1.02*2^-11 (||e-eh|| <= 2^-11*||e||, ||e||<=1.01), Me = 1.01.
    const float btok = 2.f * (sqrtf(s1) * 5.0e-4f + sqrtf(s2) * 1.01f) + 0.02f;

    const float* gm = g_gmin + (size_t)n * NGRP;
    float gv[32];
    float vmin = 3.402823466e+38f;
#pragma unroll
    for (int i = 0; i < 32; ++i) {
        gv[i] = __ldg(&gm[i * 32 + lane]);
        vmin = fminf(vmin, gv[i]);
    }
#pragma unroll
    for (int off = 16; off; off >>= 1)
        vmin = fminf(vmin, __shfl_xor_sync(0xffffffffu, vmin, off));
    const float thresh = vmin + btok;

    float ebest = 3.402823466e+38f;
    int   eidx  = 0;
#pragma unroll
    for (int i = 0; i < 32; ++i) {
        unsigned mask = __ballot_sync(0xffffffffu, gv[i] <= thresh);
        while (mask) {
            int j = __ffs(mask) - 1; mask &= mask - 1;
            int k0 = (i * 32 + j) * 8;
#pragma unroll
            for (int c = 0; c < 8; ++c) {
                int k = k0 + c;
                const float* er = g_ET + (size_t)k * D_;
                float p = 0.f;
#pragma unroll
                for (int jj = 0; jj < 8; ++jj)
                    p = fmaf(xv[jj], __ldg(&er[lane + jj * 32]), p);
#pragma unroll
                for (int off = 16; off; off >>= 1)
                    p += __shfl_xor_sync(0xffffffffu, p, off);
                float ed = fmaf(-2.f, p, __ldg(&g_csq[k]));
                if (ed < ebest) { ebest = ed; eidx = k; }
            }
        }
    }
    if (lane == 0) g_ind[n] = eidx;
}

// ---------------------------------------------------------------------------
// Outputs (4 tokens per thread, vectorized): exact fp32 op order for STE.
// ---------------------------------------------------------------------------
__global__ void vq_gather_kernel(const float* __restrict__ x,
                                 const float* __restrict__ E,
                                 float* __restrict__ out) {
    size_t t = (size_t)blockIdx.x * blockDim.x + threadIdx.x;  // D_*NTOK/4
    int n4 = (int)(t & (NTOK / 4 - 1));
    int d  = (int)(t >> 12);
    int n  = n4 * 4;
    int b = n >> 10;
    int s = n & (S_ - 1);
    int i0 = g_ind[n];
    int i1 = g_ind[n + 1];
    int i2 = g_ind[n + 2];
    int i3 = g_ind[n + 3];
    const float* Ed = E + (size_t)d * KC;
    float4 q = make_float4(Ed[i0], Ed[i1], Ed[i2], Ed[i3]);
    size_t xo = ((size_t)b * D_ + d) * S_ + s;
    float4 xv = *(const float4*)&x[xo];
    float4 o1 = make_float4(xv.x + (q.x - xv.x), xv.y + (q.y - xv.y),
                            xv.z + (q.z - xv.z), xv.w + (q.w - xv.w));
    *(float4*)&out[xo]       = o1;
    *(float4*)&out[BDS + xo] = q;
    if (d == 0)
        *(float4*)&out[2 * (size_t)BDS + n] =
            make_float4((float)i0, (float)i1, (float)i2, (float)i3);
}

// ---------------------------------------------------------------------------
extern "C" void kernel_launch(void* const* d_in, const int* in_sizes, int n_in,
                              void* d_out, int out_size) {
    const float* x = (const float*)d_in[0];   // [B, D, H, W] fp32
    const float* E = (const float*)d_in[1];   // [D, K] fp32
    float* out = (float*)d_out;

    cudaFuncSetAttribute(vq_mma_kernel,
                         cudaFuncAttributeMaxDynamicSharedMemorySize, SMEM_MAIN);

    vq_split_xe<<<MB_TOT + KC / 32, 256>>>(x, E);
    vq_mma_kernel<<<(NTOK / MT) * NPARTS, 256, SMEM_MAIN>>>();
    vq_finalize<<<NTOK / 8, 256>>>(x);
    vq_gather_kernel<<<(D_ * NTOK / 4) / 256, 256>>>(x, E, out);
}

// round 13
// speedup vs baseline: 1.5667x; 1.5667x over previous
#include <cuda_runtime.h>
#include <cuda_fp16.h>
#include <cstdint>

// Problem constants
#define B_    16
#define D_    256
#define S_    1024
#define NTOK  16384
#define KC    8192
#define BDS   4194304
#define NGRP  1024                // KC/8 code-groups of 8

#define MB_TOT (NTOK / 16)        // 1024 token blocks of 16
#define KS_TOT (D_ / 16)          // 16 k-steps of 16

// Main kernel tiling (8 warps, 4m x 4n warp microtiles), hi-only MMA
#define MT     128
#define NT     128
#define NPARTS 8
#define NITERL 64                 // 8 tiles x 8 kspairs

// smem: A hi tile + gmin staging
#define SMEM_A_BYTES 65536        // [8 mb][16 ks][32 lane][4] u32
#define SMEM_GM      8192         // [128][16] floats
#define SMEM_MAIN (SMEM_A_BYTES + SMEM_GM)

// Device scratch (allocations forbidden)
__device__ uint32_t g_Ah[MB_TOT * KS_TOT * 32 * 4];   // 8 MB hi A-fragments
__device__ uint32_t g_B [NGRP * 8 * 32 * 4];          // 4 MB hi B-fragments
__device__ float    g_ET[KC * D_];                    // 8 MB code-major E (fp32)
__device__ float    g_csq[KC];
__device__ float    g_gmin[(size_t)NTOK * NGRP];      // 64 MB group minima
__device__ int      g_ind[NTOK];

// ---------------------------- helpers --------------------------------------
__device__ __forceinline__ uint32_t smem_u32(const void* p) {
    uint32_t a;
    asm("{ .reg .u64 t; cvta.to.shared.u64 t, %1; cvt.u32.u64 %0, t; }" : "=r"(a) : "l"(p));
    return a;
}
__device__ __forceinline__ void cpasync16(uint32_t dst, const void* src) {
    asm volatile("cp.async.cg.shared.global [%0], [%1], 16;" :: "r"(dst), "l"(src));
}
__device__ __forceinline__ void mma16816(float* c, const uint32_t* a, const uint32_t* b) {
    asm volatile("mma.sync.aligned.m16n8k16.row.col.f32.f16.f16.f32 "
                 "{%0,%1,%2,%3}, {%4,%5,%6,%7}, {%8,%9}, {%0,%1,%2,%3};"
                 : "+f"(c[0]), "+f"(c[1]), "+f"(c[2]), "+f"(c[3])
                 : "r"(a[0]), "r"(a[1]), "r"(a[2]), "r"(a[3]), "r"(b[0]), "r"(b[1]));
}
__device__ __forceinline__ uint32_t pack_h2(__half lo, __half hi) {
    __half2 h = __halves2half2(lo, hi);
    return *reinterpret_cast<uint32_t*>(&h);
}

// ---------------------------------------------------------------------------
// Fused preprocessing. Blocks [0, MB_TOT): x -> hi A-fragments.
// Blocks [MB_TOT, +KC/32): E -> hi B-fragments + csq + code-major E_T.
// ---------------------------------------------------------------------------
__global__ void vq_split_xe(const float* __restrict__ x,
                            const float* __restrict__ E) {
    __shared__ char sm[36000];
    const int tid = threadIdx.x;

    if (blockIdx.x < MB_TOT) {
        float* xs = (float*)sm;                  // [d][tok] 16 KB
        const int mb = blockIdx.x;
        const int t0 = mb * 16;
        const int b  = t0 >> 10;
        const int s0 = t0 & (S_ - 1);

        for (int i = tid; i < D_ * 16; i += 256) {
            int d = i >> 4, tok = i & 15;
            xs[d * 16 + tok] = x[((size_t)b * D_ + d) * S_ + s0 + tok];
        }
        __syncthreads();

        const size_t obase = (size_t)mb * (KS_TOT * 32 * 4);
        for (int oi = tid; oi < KS_TOT * 32 * 4; oi += 256) {
            int ks = oi >> 7, rem = oi & 127;
            int lane = rem >> 2, r = rem & 3;
            int gid = lane >> 2, tig = lane & 3;
            int row = gid + (r & 1) * 8;
            int c0  = ks * 16 + tig * 2 + (r >> 1) * 8;
            float v0 = xs[c0 * 16 + row];
            float v1 = xs[(c0 + 1) * 16 + row];
            g_Ah[obase + oi] = pack_h2(__float2half_rn(v0), __float2half_rn(v1));
        }
    } else {
        float* es   = (float*)sm;                // [256][33] padded, 33.8 KB
        float* cred = (float*)(sm + 33792);      // [8][32]
        const int eb = blockIdx.x - MB_TOT;
        const int k0 = eb * 32;

        for (int i = tid; i < D_ * 32; i += 256) {
            int d = i >> 5, kk = i & 31;
            es[d * 33 + kk] = E[(size_t)d * KC + k0 + kk];
        }
        __syncthreads();

        {   // csq: deterministic part-ordered sum of squares per code column.
            const int kk = tid & 31, part = tid >> 5;
            float s = 0.f;
#pragma unroll 8
            for (int dd = 0; dd < 32; ++dd) {
                float v = es[(part * 32 + dd) * 33 + kk];
                s = fmaf(v, v, s);
            }
            cred[part * 32 + kk] = s;
        }
        __syncthreads();
        if (tid < 32) {
            float s = cred[tid];
#pragma unroll
            for (int p = 1; p < 8; ++p) s += cred[p * 32 + tid];
            g_csq[k0 + tid] = s;
        }

        // Code-major fp32 copy E_T[k][d] (for the exact verification pass).
        for (int i = tid; i < 2048; i += 256) {
            int kl = i >> 6, d4 = (i & 63) * 4;
            float4 v;
            v.x = es[(d4 + 0) * 33 + kl];
            v.y = es[(d4 + 1) * 33 + kl];
            v.z = es[(d4 + 2) * 33 + kl];
            v.w = es[(d4 + 3) * 33 + kl];
            *(float4*)&g_ET[(size_t)(k0 + kl) * D_ + d4] = v;
        }

        // Hi B-fragments: [nb][kspair][lane] uint4 = {ks0r0, ks0r1, ks1r0, ks1r1}.
        for (int fi = tid; fi < 1024; fi += 256) {
            int nbl    = fi >> 8;                // 0..3
            int kspair = (fi >> 5) & 7;
            int lane   = fi & 31;
            int gid = lane >> 2, tig = lane & 3;
            int kl  = nbl * 8 + gid;
            uint32_t frag[4];
#pragma unroll
            for (int ksl = 0; ksl < 2; ++ksl)
#pragma unroll
                for (int r = 0; r < 2; ++r) {
                    int d0 = (kspair * 2 + ksl) * 16 + tig * 2 + r * 8;
                    frag[ksl * 2 + r] = pack_h2(__float2half_rn(es[d0 * 33 + kl]),
                                                __float2half_rn(es[(d0 + 1) * 33 + kl]));
                }
            *(uint4*)&g_B[(((size_t)(eb * 4 + nbl) * 8 + kspair) * 32 + lane) * 4] =
                *(uint4*)frag;
        }
    }
}

// ---------------------------------------------------------------------------
// Pass 1: hi*hi MMA only; per-(token, 8-code-group) approx minima to g_gmin.
// ---------------------------------------------------------------------------
__device__ __forceinline__ void loadB(uint4* bnew, int it, int nwarp, int lane) {
    const int ntile = it >> 3, kspair = it & 7;
    const uint4* base = (const uint4*)g_B +
        (((size_t)(ntile * 16 + nwarp * 4) * 8 + kspair) * 32 + lane);
#pragma unroll
    for (int nf = 0; nf < 4; ++nf)
        bnew[nf] = __ldg(base + nf * 256);       // nf stride: 8*32 uint4
}

#define MMA_ITER(II)                                                          \
    do {                                                                      \
        const int it = it0 + (II);                                            \
        const int ntile = it >> 3, kspair = it & 7;                           \
        uint4 bcur[4];                                                        \
        _Pragma("unroll")                                                     \
        for (int q = 0; q < 4; ++q) bcur[q] = bnxt[q];                        \
        if ((II) + 1 < NITERL) loadB(bnxt, it + 1, nwarp, lane);              \
        if (kspair == 0) {                                                    \
            _Pragma("unroll")                                                 \
            for (int mf = 0; mf < 4; ++mf)                                    \
                _Pragma("unroll")                                             \
                for (int nf = 0; nf < 4; ++nf)                                \
                    _Pragma("unroll")                                         \
                    for (int c = 0; c < 4; ++c) acc[mf][nf][c] = 0.f;         \
            _Pragma("unroll")                                                 \
            for (int nf = 0; nf < 4; ++nf) {                                  \
                int kq = ntile * NT + (nwarp * 4 + nf) * 8 + tig * 2;         \
                cregs[nf][0] = __ldg(&g_csq[kq]);                             \
                cregs[nf][1] = __ldg(&g_csq[kq + 1]);                         \
            }                                                                 \
        }                                                                     \
        _Pragma("unroll")                                                     \
        for (int ksl = 0; ksl < 2; ++ksl) {                                   \
            const int ks = kspair * 2 + ksl;                                  \
            uint32_t ah[4][4];                                                \
            _Pragma("unroll")                                                 \
            for (int mf = 0; mf < 4; ++mf)                                    \
                *(uint4*)ah[mf] =                                             \
                    *(const uint4*)(As + (((mwarp * 4 + mf) * 16 + ks) * 32 + lane) * 4); \
            _Pragma("unroll")                                                 \
            for (int mf = 0; mf < 4; ++mf)                                    \
                _Pragma("unroll")                                             \
                for (int nf = 0; nf < 4; ++nf)                                \
                    mma16816(acc[mf][nf], ah[mf],                             \
                             ((const uint32_t*)&bcur[nf]) + ksl * 2);         \
        }                                                                     \
        if (kspair == 7) {                                                    \
            _Pragma("unroll")                                                 \
            for (int mf = 0; mf < 4; ++mf)                                    \
                _Pragma("unroll")                                             \
                for (int hh = 0; hh < 2; ++hh)                                \
                    _Pragma("unroll")                                         \
                    for (int nf = 0; nf < 4; ++nf) {                          \
                        float m0 = fmaf(-2.f, acc[mf][nf][hh * 2],     cregs[nf][0]); \
                        float m1 = fmaf(-2.f, acc[mf][nf][hh * 2 + 1], cregs[nf][1]); \
                        float gm = fminf(m0, m1);                             \
                        gm = fminf(gm, __shfl_xor_sync(0xffffffffu, gm, 1));  \
                        gm = fminf(gm, __shfl_xor_sync(0xffffffffu, gm, 2));  \
                        if (tig == 0)                                         \
                            sgm[(mwarp * 64 + mf * 16 + hh * 8 + gid) * 16 +  \
                                nwarp * 4 + nf] = gm;                         \
                    }                                                         \
            __syncthreads();                                                  \
            {                                                                 \
                int r = tid >> 1, c0 = (tid & 1) * 8;                         \
                float4 va = *(float4*)&sgm[r * 16 + c0];                      \
                float4 vb = *(float4*)&sgm[r * 16 + c0 + 4];                  \
                float* dst = &g_gmin[(size_t)(n0 + r) * NGRP + ntile * 16 + c0]; \
                *(float4*)dst = va;                                           \
                *(float4*)(dst + 4) = vb;                                     \
            }                                                                 \
            __syncthreads();                                                  \
        }                                                                     \
    } while (0)

__global__ __launch_bounds__(256, 1) void vq_mma_kernel() {
    extern __shared__ char smem[];
    uint32_t* As = (uint32_t*)smem;
    float* sgm = (float*)(smem + SMEM_A_BYTES);
    const uint32_t sA = smem_u32(As);

    const int tid = threadIdx.x;
    const int wid = tid >> 5, lane = tid & 31;
    const int gid = lane >> 2, tig = lane & 3;
    const int mwarp = wid >> 2, nwarp = wid & 3;

    const int bx = blockIdx.x;                // 0..1023
    const int part   = bx & (NPARTS - 1);
    const int tileid = bx >> 3;
    const int mb0 = tileid * 8;
    const int n0  = tileid * MT;
    const int it0 = part * NITERL;

    // B pipeline head first (LDGs in flight during the A prologue).
    uint4 bnxt[4];
    loadB(bnxt, it0, nwarp, lane);

    // A prologue (hi only, 64 KB) in two commit groups: ks 0-7, ks 8-15.
    {
        const uint32_t* srcH = g_Ah + (size_t)mb0 * (KS_TOT * 32 * 4);
#pragma unroll
        for (int half = 0; half < 2; ++half) {
            for (int u = tid; u < 2048; u += 256) {
                int mb = u >> 8, ks = ((u >> 5) & 7) + half * 8, ln = u & 31;
                int unit = (mb * 16 + ks) * 32 + ln;     // 16-byte units
                cpasync16(sA + unit * 16, srcH + unit * 4);
            }
            asm volatile("cp.async.commit_group;" ::: "memory");
        }
    }

    float acc[4][4][4];
    float cregs[4][2];

    asm volatile("cp.async.wait_group 1;" ::: "memory");
    __syncthreads();
#pragma unroll 1
    for (int ii = 0; ii < 4; ++ii) MMA_ITER(ii);

    asm volatile("cp.async.wait_group 0;" ::: "memory");
    __syncthreads();
#pragma unroll 1
    for (int ii = 4; ii < NITERL; ++ii) MMA_ITER(ii);
}

// ---------------------------------------------------------------------------
// Pass 2: exact fp32 verification. One warp per token.
// thresh = min(gmin) + 2(||xh||*Mel + ||x-xh||*Me) + eps; exact-scan all
// qualifying 8-code groups in ascending k; lowest index wins ties.
// ---------------------------------------------------------------------------
__global__ __launch_bounds__(256, 1) void vq_finalize(const float* __restrict__ x) {
    const int tid = threadIdx.x;
    const int wid = tid >> 5, lane = tid & 31;
    const int n = blockIdx.x * 8 + wid;
    const int b = n >> 10, s = n & (S_ - 1);

    float xv[8];
    const float* xb = x + ((size_t)b * D_) * S_ + s;
#pragma unroll
    for (int j = 0; j < 8; ++j) xv[j] = __ldg(&xb[(size_t)(lane + j * 32) * S_]);

    // Actual hi/residual norms (same rounding as the fragments).
    float s1 = 0.f, s2 = 0.f;
#pragma unroll
    for (int j = 0; j < 8; ++j) {
        float h = __half2float(__float2half_rn(xv[j]));
        float r = xv[j] - h;
        s1 = fmaf(h, h, s1);
        s2 = fmaf(r, r, s2);
    }
#pragma unroll
    for (int off = 16; off; off >>= 1) {
        s1 += __shfl_xor_sync(0xffffffffu, s1, off);
        s2 += __shfl_xor_sync(0xffffffffu, s2, off);
    }
    // Mel = 1.02*2^-11 (||e-eh|| <= 2^-11*||e||, ||e||<=1.01), Me = 1.01.
    const float btok = 2.f * (sqrtf(s1) * 5.0e-4f + sqrtf(s2) * 1.01f) + 0.02f;

    const float* gm = g_gmin + (size_t)n * NGRP;
    float gv[32];
    float vmin = 3.402823466e+38f;
#pragma unroll
    for (int i = 0; i < 32; ++i) {
        gv[i] = __ldg(&gm[i * 32 + lane]);
        vmin = fminf(vmin, gv[i]);
    }
#pragma unroll
    for (int off = 16; off; off >>= 1)
        vmin = fminf(vmin, __shfl_xor_sync(0xffffffffu, vmin, off));
    const float thresh = vmin + btok;

    float ebest = 3.402823466e+38f;
    int   eidx  = 0;
#pragma unroll
    for (int i = 0; i < 32; ++i) {
        unsigned mask = __ballot_sync(0xffffffffu, gv[i] <= thresh);
        while (mask) {
            int j = __ffs(mask) - 1; mask &= mask - 1;
            int k0 = (i * 32 + j) * 8;
#pragma unroll
            for (int c = 0; c < 8; ++c) {
                int k = k0 + c;
                const float* er = g_ET + (size_t)k * D_;
                float p = 0.f;
#pragma unroll
                for (int jj = 0; jj < 8; ++jj)
                    p = fmaf(xv[jj], __ldg(&er[lane + jj * 32]), p);
#pragma unroll
                for (int off = 16; off; off >>= 1)
                    p += __shfl_xor_sync(0xffffffffu, p, off);
                float ed = fmaf(-2.f, p, __ldg(&g_csq[k]));
                if (ed < ebest) { ebest = ed; eidx = k; }
            }
        }
    }
    if (lane == 0) g_ind[n] = eidx;
}

// ---------------------------------------------------------------------------
// Outputs (4 tokens per thread, vectorized): exact fp32 op order for STE.
// ---------------------------------------------------------------------------
__global__ void vq_gather_kernel(const float* __restrict__ x,
                                 const float* __restrict__ E,
                                 float* __restrict__ out) {
    size_t t = (size_t)blockIdx.x * blockDim.x + threadIdx.x;  // D_*NTOK/4
    int n4 = (int)(t & (NTOK / 4 - 1));
    int d  = (int)(t >> 12);
    int n  = n4 * 4;
    int b = n >> 10;
    int s = n & (S_ - 1);
    int i0 = g_ind[n];
    int i1 = g_ind[n + 1];
    int i2 = g_ind[n + 2];
    int i3 = g_ind[n + 3];
    const float* Ed = E + (size_t)d * KC;
    float4 q = make_float4(Ed[i0], Ed[i1], Ed[i2], Ed[i3]);
    size_t xo = ((size_t)b * D_ + d) * S_ + s;
    float4 xv = *(const float4*)&x[xo];
    float4 o1 = make_float4(xv.x + (q.x - xv.x), xv.y + (q.y - xv.y),
                            xv.z + (q.z - xv.z), xv.w + (q.w - xv.w));
    *(float4*)&out[xo]       = o1;
    *(float4*)&out[BDS + xo] = q;
    if (d == 0)
        *(float4*)&out[2 * (size_t)BDS + n] =
            make_float4((float)i0, (float)i1, (float)i2, (float)i3);
}

// ---------------------------------------------------------------------------
extern "C" void kernel_launch(void* const* d_in, const int* in_sizes, int n_in,
                              void* d_out, int out_size) {
    const float* x = (const float*)d_in[0];   // [B, D, H, W] fp32
    const float* E = (const float*)d_in[1];   // [D, K] fp32
    float* out = (float*)d_out;

    cudaFuncSetAttribute(vq_mma_kernel,
                         cudaFuncAttributeMaxDynamicSharedMemorySize, SMEM_MAIN);

    vq_split_xe<<<MB_TOT + KC / 32, 256>>>(x, E);
    vq_mma_kernel<<<(NTOK / MT) * NPARTS, 256, SMEM_MAIN>>>();
    vq_finalize<<<NTOK / 8, 256>>>(x);
    vq_gather_kernel<<<(D_ * NTOK / 4) / 256, 256>>>(x, E, out);
}

// round 14
// speedup vs baseline: 1.6748x; 1.0690x over previous
#include <cuda_runtime.h>
#include <cuda_fp16.h>
#include <cstdint>

// Problem constants
#define B_    16
#define D_    256
#define S_    1024
#define NTOK  16384
#define KC    8192
#define BDS   4194304
#define NGRP  1024                // KC/8 code-groups of 8

#define MB_TOT (NTOK / 16)        // 1024 token blocks of 16
#define KS_TOT (D_ / 16)          // 16 k-steps of 16

// Main kernel tiling (8 warps, 4m x 4n warp microtiles), hi-only MMA
#define MT     128
#define NT     128
#define NPARTS 8
#define NITERL 64                 // 8 tiles x 8 kspairs

// smem: A hi tile + double-buffered gmin staging ([row][grp][tig], stride 68)
#define SMEM_A_BYTES 65536        // [8 mb][16 ks][32 lane][4] u32
#define SGM_STRIDE   68           // floats per row (17*4: conflict-free)
#define SGM_FLOATS   (MT * SGM_STRIDE)          // 8704 floats = 34816 B
#define SMEM_MAIN (SMEM_A_BYTES + 2 * SGM_FLOATS * 4)   // 135168 B

// Device scratch (allocations forbidden)
__device__ uint32_t g_Ah[MB_TOT * KS_TOT * 32 * 4];   // 8 MB hi A-fragments
__device__ uint32_t g_B [NGRP * 8 * 32 * 4];          // 4 MB hi B-fragments
__device__ float    g_ET[KC * D_];                    // 8 MB code-major E (fp32)
__device__ float    g_csq[KC];
__device__ float    g_bt[NTOK];                       // per-token bound
__device__ float    g_gmin[(size_t)NTOK * NGRP];      // 64 MB group minima
__device__ int      g_ind[NTOK];

// ---------------------------- helpers --------------------------------------
__device__ __forceinline__ uint32_t smem_u32(const void* p) {
    uint32_t a;
    asm("{ .reg .u64 t; cvta.to.shared.u64 t, %1; cvt.u32.u64 %0, t; }" : "=r"(a) : "l"(p));
    return a;
}
__device__ __forceinline__ void cpasync16(uint32_t dst, const void* src) {
    asm volatile("cp.async.cg.shared.global [%0], [%1], 16;" :: "r"(dst), "l"(src));
}
__device__ __forceinline__ void mma16816(float* c, const uint32_t* a, const uint32_t* b) {
    asm volatile("mma.sync.aligned.m16n8k16.row.col.f32.f16.f16.f32 "
                 "{%0,%1,%2,%3}, {%4,%5,%6,%7}, {%8,%9}, {%0,%1,%2,%3};"
                 : "+f"(c[0]), "+f"(c[1]), "+f"(c[2]), "+f"(c[3])
                 : "r"(a[0]), "r"(a[1]), "r"(a[2]), "r"(a[3]), "r"(b[0]), "r"(b[1]));
}
__device__ __forceinline__ uint32_t pack_h2(__half lo, __half hi) {
    __half2 h = __halves2half2(lo, hi);
    return *reinterpret_cast<uint32_t*>(&h);
}

// ---------------------------------------------------------------------------
// Fused preprocessing. Blocks [0, MB_TOT): x -> hi A-fragments + btok.
// Blocks [MB_TOT, +KC/32): E -> hi B-fragments + csq + code-major E_T.
// ---------------------------------------------------------------------------
__global__ void vq_split_xe(const float* __restrict__ x,
                            const float* __restrict__ E) {
    __shared__ char sm[36000];
    const int tid = threadIdx.x;

    if (blockIdx.x < MB_TOT) {
        float* xs = (float*)sm;                  // [d][tok] 16 KB
        float* nr = (float*)(sm + 16384);        // [2][16 part][16 tok]
        const int mb = blockIdx.x;
        const int t0 = mb * 16;
        const int b  = t0 >> 10;
        const int s0 = t0 & (S_ - 1);

        for (int i = tid; i < D_ * 16; i += 256) {
            int d = i >> 4, tok = i & 15;
            xs[d * 16 + tok] = x[((size_t)b * D_ + d) * S_ + s0 + tok];
        }
        __syncthreads();

        // Per-token hi/residual norms for the verification bound.
        {
            const int tok = tid & 15, part = tid >> 4;
            float s1 = 0.f, s2 = 0.f;
#pragma unroll
            for (int dd = 0; dd < 16; ++dd) {
                float v = xs[(part * 16 + dd) * 16 + tok];
                float h = __half2float(__float2half_rn(v));
                float r = v - h;
                s1 = fmaf(h, h, s1);
                s2 = fmaf(r, r, s2);
            }
            nr[part * 16 + tok] = s1;
            nr[256 + part * 16 + tok] = s2;
        }
        __syncthreads();
        if (tid < 16) {
            float s1 = 0.f, s2 = 0.f;
#pragma unroll
            for (int p = 0; p < 16; ++p) {
                s1 += nr[p * 16 + tid];
                s2 += nr[256 + p * 16 + tid];
            }
            // Mel = 1.02*2^-11 with ||e|| <= 1.01; Me = 1.01; + eps slack.
            g_bt[t0 + tid] = 2.f * (sqrtf(s1) * 5.0e-4f + sqrtf(s2) * 1.01f) + 0.02f;
        }

        const size_t obase = (size_t)mb * (KS_TOT * 32 * 4);
        for (int oi = tid; oi < KS_TOT * 32 * 4; oi += 256) {
            int ks = oi >> 7, rem = oi & 127;
            int lane = rem >> 2, r = rem & 3;
            int gid = lane >> 2, tig = lane & 3;
            int row = gid + (r & 1) * 8;
            int c0  = ks * 16 + tig * 2 + (r >> 1) * 8;
            float v0 = xs[c0 * 16 + row];
            float v1 = xs[(c0 + 1) * 16 + row];
            g_Ah[obase + oi] = pack_h2(__float2half_rn(v0), __float2half_rn(v1));
        }
    } else {
        float* es   = (float*)sm;                // [256][33] padded, 33.8 KB
        float* cred = (float*)(sm + 33792);      // [8][32]
        const int eb = blockIdx.x - MB_TOT;
        const int k0 = eb * 32;

        for (int i = tid; i < D_ * 32; i += 256) {
            int d = i >> 5, kk = i & 31;
            es[d * 33 + kk] = E[(size_t)d * KC + k0 + kk];
        }
        __syncthreads();

        {   // csq: deterministic part-ordered sum of squares per code column.
            const int kk = tid & 31, part = tid >> 5;
            float s = 0.f;
#pragma unroll 8
            for (int dd = 0; dd < 32; ++dd) {
                float v = es[(part * 32 + dd) * 33 + kk];
                s = fmaf(v, v, s);
            }
            cred[part * 32 + kk] = s;
        }
        __syncthreads();
        if (tid < 32) {
            float s = cred[tid];
#pragma unroll
            for (int p = 1; p < 8; ++p) s += cred[p * 32 + tid];
            g_csq[k0 + tid] = s;
        }

        // Code-major fp32 copy E_T[k][d] (for the exact verification pass).
        for (int i = tid; i < 2048; i += 256) {
            int kl = i >> 6, d4 = (i & 63) * 4;
            float4 v;
            v.x = es[(d4 + 0) * 33 + kl];
            v.y = es[(d4 + 1) * 33 + kl];
            v.z = es[(d4 + 2) * 33 + kl];
            v.w = es[(d4 + 3) * 33 + kl];
            *(float4*)&g_ET[(size_t)(k0 + kl) * D_ + d4] = v;
        }

        // Hi B-fragments: [nb][kspair][lane] uint4 = {ks0r0, ks0r1, ks1r0, ks1r1}.
        for (int fi = tid; fi < 1024; fi += 256) {
            int nbl    = fi >> 8;
            int kspair = (fi >> 5) & 7;
            int lane   = fi & 31;
            int gid = lane >> 2, tig = lane & 3;
            int kl  = nbl * 8 + gid;
            uint32_t frag[4];
#pragma unroll
            for (int ksl = 0; ksl < 2; ++ksl)
#pragma unroll
                for (int r = 0; r < 2; ++r) {
                    int d0 = (kspair * 2 + ksl) * 16 + tig * 2 + r * 8;
                    frag[ksl * 2 + r] = pack_h2(__float2half_rn(es[d0 * 33 + kl]),
                                                __float2half_rn(es[(d0 + 1) * 33 + kl]));
                }
            *(uint4*)&g_B[(((size_t)(eb * 4 + nbl) * 8 + kspair) * 32 + lane) * 4] =
                *(uint4*)frag;
        }
    }
}

// ---------------------------------------------------------------------------
// Pass 1: hi*hi MMA only; per-(token, 8-code-group) approx minima to g_gmin.
// Epilogue: STS to padded smem (no shfl), 1 barrier, coalesced fold+store.
// ---------------------------------------------------------------------------
__device__ __forceinline__ void loadB(uint4* bnew, int it, int nwarp, int lane) {
    const int ntile = it >> 3, kspair = it & 7;
    const uint4* base = (const uint4*)g_B +
        (((size_t)(ntile * 16 + nwarp * 4) * 8 + kspair) * 32 + lane);
#pragma unroll
    for (int nf = 0; nf < 4; ++nf)
        bnew[nf] = __ldg(base + nf * 256);       // nf stride: 8*32 uint4
}

#define MMA_ITER(II)                                                          \
    do {                                                                      \
        const int it = it0 + (II);                                            \
        const int ntile = it >> 3, kspair = it & 7;                           \
        uint4 bcur[4];                                                        \
        _Pragma("unroll")                                                     \
        for (int q = 0; q < 4; ++q) bcur[q] = bnxt[q];                        \
        if ((II) + 1 < NITERL) loadB(bnxt, it + 1, nwarp, lane);              \
        if (kspair == 0) {                                                    \
            _Pragma("unroll")                                                 \
            for (int mf = 0; mf < 4; ++mf)                                    \
                _Pragma("unroll")                                             \
                for (int nf = 0; nf < 4; ++nf)                                \
                    _Pragma("unroll")                                         \
                    for (int c = 0; c < 4; ++c) acc[mf][nf][c] = 0.f;         \
            _Pragma("unroll")                                                 \
            for (int nf = 0; nf < 4; ++nf) {                                  \
                int kq = ntile * NT + (nwarp * 4 + nf) * 8 + tig * 2;         \
                cregs[nf][0] = __ldg(&g_csq[kq]);                             \
                cregs[nf][1] = __ldg(&g_csq[kq + 1]);                         \
            }                                                                 \
        }                                                                     \
        _Pragma("unroll")                                                     \
        for (int ksl = 0; ksl < 2; ++ksl) {                                   \
            const int ks = kspair * 2 + ksl;                                  \
            uint32_t ah[4][4];                                                \
            _Pragma("unroll")                                                 \
            for (int mf = 0; mf < 4; ++mf)                                    \
                *(uint4*)ah[mf] =                                             \
                    *(const uint4*)(As + (((mwarp * 4 + mf) * 16 + ks) * 32 + lane) * 4); \
            _Pragma("unroll")                                                 \
            for (int mf = 0; mf < 4; ++mf)                                    \
                _Pragma("unroll")                                             \
                for (int nf = 0; nf < 4; ++nf)                                \
                    mma16816(acc[mf][nf], ah[mf],                             \
                             ((const uint32_t*)&bcur[nf]) + ksl * 2);         \
        }                                                                     \
        if (kspair == 7) {                                                    \
            float* sg = sgm + (ntile & 1) * SGM_FLOATS;                       \
            _Pragma("unroll")                                                 \
            for (int mf = 0; mf < 4; ++mf)                                    \
                _Pragma("unroll")                                             \
                for (int hh = 0; hh < 2; ++hh)                                \
                    _Pragma("unroll")                                         \
                    for (int nf = 0; nf < 4; ++nf) {                          \
                        float m0 = fmaf(-2.f, acc[mf][nf][hh * 2],     cregs[nf][0]); \
                        float m1 = fmaf(-2.f, acc[mf][nf][hh * 2 + 1], cregs[nf][1]); \
                        int row = mwarp * 64 + mf * 16 + hh * 8 + gid;        \
                        sg[row * SGM_STRIDE + (nwarp * 4 + nf) * 4 + tig] =   \
                            fminf(m0, m1);                                    \
                    }                                                         \
            __syncthreads();                                                  \
            {                                                                 \
                int r = tid >> 1, c0 = (tid & 1) * 8;                         \
                float o8[8];                                                  \
                _Pragma("unroll")                                             \
                for (int g = 0; g < 8; ++g) {                                 \
                    float4 t4 = *(float4*)&sg[r * SGM_STRIDE + (c0 + g) * 4]; \
                    o8[g] = fminf(fminf(t4.x, t4.y), fminf(t4.z, t4.w));      \
                }                                                             \
                float* dst = &g_gmin[(size_t)(n0 + r) * NGRP + ntile * 16 + c0]; \
                *(float4*)dst = make_float4(o8[0], o8[1], o8[2], o8[3]);      \
                *(float4*)(dst + 4) = make_float4(o8[4], o8[5], o8[6], o8[7]);\
            }                                                                 \
        }                                                                     \
    } while (0)

__global__ __launch_bounds__(256, 1) void vq_mma_kernel() {
    extern __shared__ char smem[];
    uint32_t* As = (uint32_t*)smem;
    float* sgm = (float*)(smem + SMEM_A_BYTES);
    const uint32_t sA = smem_u32(As);

    const int tid = threadIdx.x;
    const int wid = tid >> 5, lane = tid & 31;
    const int gid = lane >> 2, tig = lane & 3;
    const int mwarp = wid >> 2, nwarp = wid & 3;

    const int bx = blockIdx.x;                // 0..1023
    const int part   = bx & (NPARTS - 1);
    const int tileid = bx >> 3;
    const int mb0 = tileid * 8;
    const int n0  = tileid * MT;
    const int it0 = part * NITERL;

    // B pipeline head first (LDGs in flight during the A prologue).
    uint4 bnxt[4];
    loadB(bnxt, it0, nwarp, lane);

    // A prologue (hi only, 64 KB) in two commit groups: ks 0-7, ks 8-15.
    {
        const uint32_t* srcH = g_Ah + (size_t)mb0 * (KS_TOT * 32 * 4);
#pragma unroll
        for (int half = 0; half < 2; ++half) {
            for (int u = tid; u < 2048; u += 256) {
                int mb = u >> 8, ks = ((u >> 5) & 7) + half * 8, ln = u & 31;
                int unit = (mb * 16 + ks) * 32 + ln;     // 16-byte units
                cpasync16(sA + unit * 16, srcH + unit * 4);
            }
            asm volatile("cp.async.commit_group;" ::: "memory");
        }
    }

    float acc[4][4][4];
    float cregs[4][2];

    asm volatile("cp.async.wait_group 1;" ::: "memory");
    __syncthreads();
#pragma unroll 1
    for (int ii = 0; ii < 4; ++ii) MMA_ITER(ii);

    asm volatile("cp.async.wait_group 0;" ::: "memory");
    __syncthreads();
#pragma unroll 1
    for (int ii = 4; ii < NITERL; ++ii) MMA_ITER(ii);
}

// ---------------------------------------------------------------------------
// Pass 2: exact fp32 verification. One warp per token.
// thresh = min(gmin) + g_bt[n]; exact-scan qualifying 8-code groups in
// ascending k; lowest index wins ties.
// ---------------------------------------------------------------------------
__global__ __launch_bounds__(256, 1) void vq_finalize(const float* __restrict__ x) {
    const int tid = threadIdx.x;
    const int wid = tid >> 5, lane = tid & 31;
    const int n = blockIdx.x * 8 + wid;
    const int b = n >> 10, s = n & (S_ - 1);

    float xv[8];
    const float* xb = x + ((size_t)b * D_) * S_ + s;
#pragma unroll
    for (int j = 0; j < 8; ++j) xv[j] = __ldg(&xb[(size_t)(lane + j * 32) * S_]);

    const float btok = __ldg(&g_bt[n]);

    const float* gm = g_gmin + (size_t)n * NGRP;
    float gv[32];
    float vmin = 3.402823466e+38f;
#pragma unroll
    for (int i = 0; i < 32; ++i) {
        gv[i] = __ldg(&gm[i * 32 + lane]);
        vmin = fminf(vmin, gv[i]);
    }
#pragma unroll
    for (int off = 16; off; off >>= 1)
        vmin = fminf(vmin, __shfl_xor_sync(0xffffffffu, vmin, off));
    const float thresh = vmin + btok;

    float ebest = 3.402823466e+38f;
    int   eidx  = 0;
#pragma unroll
    for (int i = 0; i < 32; ++i) {
        unsigned mask = __ballot_sync(0xffffffffu, gv[i] <= thresh);
        while (mask) {
            int j = __ffs(mask) - 1; mask &= mask - 1;
            int k0 = (i * 32 + j) * 8;
#pragma unroll
            for (int c = 0; c < 8; ++c) {
                int k = k0 + c;
                const float* er = g_ET + (size_t)k * D_;
                float p = 0.f;
#pragma unroll
                for (int jj = 0; jj < 8; ++jj)
                    p = fmaf(xv[jj], __ldg(&er[lane + jj * 32]), p);
#pragma unroll
                for (int off = 16; off; off >>= 1)
                    p += __shfl_xor_sync(0xffffffffu, p, off);
                float ed = fmaf(-2.f, p, __ldg(&g_csq[k]));
                if (ed < ebest) { ebest = ed; eidx = k; }
            }
        }
    }
    if (lane == 0) g_ind[n] = eidx;
}

// ---------------------------------------------------------------------------
// Outputs (4 tokens per thread, vectorized): exact fp32 op order for STE.
// ---------------------------------------------------------------------------
__global__ void vq_gather_kernel(const float* __restrict__ x,
                                 const float* __restrict__ E,
                                 float* __restrict__ out) {
    size_t t = (size_t)blockIdx.x * blockDim.x + threadIdx.x;  // D_*NTOK/4
    int n4 = (int)(t & (NTOK / 4 - 1));
    int d  = (int)(t >> 12);
    int n  = n4 * 4;
    int b = n >> 10;
    int s = n & (S_ - 1);
    int i0 = g_ind[n];
    int i1 = g_ind[n + 1];
    int i2 = g_ind[n + 2];
    int i3 = g_ind[n + 3];
    const float* Ed = E + (size_t)d * KC;
    float4 q = make_float4(Ed[i0], Ed[i1], Ed[i2], Ed[i3]);
    size_t xo = ((size_t)b * D_ + d) * S_ + s;
    float4 xv = *(const float4*)&x[xo];
    float4 o1 = make_float4(xv.x + (q.x - xv.x), xv.y + (q.y - xv.y),
                            xv.z + (q.z - xv.z), xv.w + (q.w - xv.w));
    *(float4*)&out[xo]       = o1;
    *(float4*)&out[BDS + xo] = q;
    if (d == 0)
        *(float4*)&out[2 * (size_t)BDS + n] =
            make_float4((float)i0, (float)i1, (float)i2, (float)i3);
}

// ---------------------------------------------------------------------------
extern "C" void kernel_launch(void* const* d_in, const int* in_sizes, int n_in,
                              void* d_out, int out_size) {
    const float* x = (const float*)d_in[0];   // [B, D, H, W] fp32
    const float* E = (const float*)d_in[1];   // [D, K] fp32
    float* out = (float*)d_out;

    cudaFuncSetAttribute(vq_mma_kernel,
                         cudaFuncAttributeMaxDynamicSharedMemorySize, SMEM_MAIN);

    vq_split_xe<<<MB_TOT + KC / 32, 256>>>(x, E);
    vq_mma_kernel<<<(NTOK / MT) * NPARTS, 256, SMEM_MAIN>>>();
    vq_finalize<<<NTOK / 8, 256>>>(x);
    vq_gather_kernel<<<(D_ * NTOK / 4) / 256, 256>>>(x, E, out);
}

// round 15
// speedup vs baseline: 1.9968x; 1.1922x over previous
#include <cuda_runtime.h>
#include <cuda_fp16.h>
#include <cstdint>

// Problem constants
#define B_    16
#define D_    256
#define S_    1024
#define NTOK  16384
#define KC    8192
#define BDS   4194304
#define NGRP  512                 // KC/16 code-groups of 16

#define MB_TOT (NTOK / 16)        // 1024 token blocks of 16
#define KS_TOT (D_ / 16)          // 16 k-steps of 16

// Main kernel tiling (8 warps, 4m x 4n warp microtiles), hi-only MMA
#define MT     128
#define NT     128
#define NPARTS 8
#define NITERL 64                 // 8 tiles x 8 kspairs

// smem: A hi tile + double-buffered gmin staging ([row][slot][tig], stride 68)
#define SMEM_A_BYTES 65536        // [8 mb][16 ks][32 lane][4] u32
#define SGM_STRIDE   68
#define SGM_FLOATS   (MT * SGM_STRIDE)          // 34816 B per buffer
#define SMEM_MAIN (SMEM_A_BYTES + 2 * SGM_FLOATS * 4)   // 135168 B

// Device scratch (allocations forbidden)
__device__ uint32_t g_Ah[MB_TOT * KS_TOT * 32 * 4];   // 8 MB hi A-fragments
__device__ uint32_t g_B [((KC / 8)) * 8 * 32 * 4];    // 4 MB hi B-fragments
__device__ float    g_ET[KC * D_];                    // 8 MB code-major E (fp32)
__device__ float    g_csq[KC];
__device__ float    g_bt[NTOK];                       // per-token bound
__device__ float    g_gmin[(size_t)NTOK * NGRP];      // 32 MB group minima
__device__ int      g_ind[NTOK];

// ---------------------------- helpers --------------------------------------
__device__ __forceinline__ uint32_t smem_u32(const void* p) {
    uint32_t a;
    asm("{ .reg .u64 t; cvta.to.shared.u64 t, %1; cvt.u32.u64 %0, t; }" : "=r"(a) : "l"(p));
    return a;
}
__device__ __forceinline__ void cpasync16(uint32_t dst, const void* src) {
    asm volatile("cp.async.cg.shared.global [%0], [%1], 16;" :: "r"(dst), "l"(src));
}
__device__ __forceinline__ void mma16816(float* c, const uint32_t* a, const uint32_t* b) {
    asm volatile("mma.sync.aligned.m16n8k16.row.col.f32.f16.f16.f32 "
                 "{%0,%1,%2,%3}, {%4,%5,%6,%7}, {%8,%9}, {%0,%1,%2,%3};"
                 : "+f"(c[0]), "+f"(c[1]), "+f"(c[2]), "+f"(c[3])
                 : "r"(a[0]), "r"(a[1]), "r"(a[2]), "r"(a[3]), "r"(b[0]), "r"(b[1]));
}
__device__ __forceinline__ uint32_t pack_h2(__half lo, __half hi) {
    __half2 h = __halves2half2(lo, hi);
    return *reinterpret_cast<uint32_t*>(&h);
}

// ---------------------------------------------------------------------------
// Fused preprocessing. Blocks [0, MB_TOT): x -> hi A-fragments + btok.
// Blocks [MB_TOT, +KC/32): E -> hi B-fragments + csq + code-major E_T.
// ---------------------------------------------------------------------------
__global__ void vq_split_xe(const float* __restrict__ x,
                            const float* __restrict__ E) {
    __shared__ char sm[36000];
    const int tid = threadIdx.x;

    if (blockIdx.x < MB_TOT) {
        float* xs = (float*)sm;                  // [d][tok] 16 KB
        float* nr = (float*)(sm + 16384);        // [2][16 part][16 tok]
        const int mb = blockIdx.x;
        const int t0 = mb * 16;
        const int b  = t0 >> 10;
        const int s0 = t0 & (S_ - 1);

        for (int i = tid; i < D_ * 16; i += 256) {
            int d = i >> 4, tok = i & 15;
            xs[d * 16 + tok] = x[((size_t)b * D_ + d) * S_ + s0 + tok];
        }
        __syncthreads();

        // Per-token hi/residual norms for the verification bound.
        {
            const int tok = tid & 15, part = tid >> 4;
            float s1 = 0.f, s2 = 0.f;
#pragma unroll
            for (int dd = 0; dd < 16; ++dd) {
                float v = xs[(part * 16 + dd) * 16 + tok];
                float h = __half2float(__float2half_rn(v));
                float r = v - h;
                s1 = fmaf(h, h, s1);
                s2 = fmaf(r, r, s2);
            }
            nr[part * 16 + tok] = s1;
            nr[256 + part * 16 + tok] = s2;
        }
        __syncthreads();
        if (tid < 16) {
            float s1 = 0.f, s2 = 0.f;
#pragma unroll
            for (int p = 0; p < 16; ++p) {
                s1 += nr[p * 16 + tid];
                s2 += nr[256 + p * 16 + tid];
            }
            // Mel = 1.02*2^-11 with ||e|| <= 1.01; Me = 1.01; + eps slack.
            g_bt[t0 + tid] = 2.f * (sqrtf(s1) * 5.0e-4f + sqrtf(s2) * 1.01f) + 0.02f;
        }

        const size_t obase = (size_t)mb * (KS_TOT * 32 * 4);
        for (int oi = tid; oi < KS_TOT * 32 * 4; oi += 256) {
            int ks = oi >> 7, rem = oi & 127;
            int lane = rem >> 2, r = rem & 3;
            int gid = lane >> 2, tig = lane & 3;
            int row = gid + (r & 1) * 8;
            int c0  = ks * 16 + tig * 2 + (r >> 1) * 8;
            float v0 = xs[c0 * 16 + row];
            float v1 = xs[(c0 + 1) * 16 + row];
            g_Ah[obase + oi] = pack_h2(__float2half_rn(v0), __float2half_rn(v1));
        }
    } else {
        float* es   = (float*)sm;                // [256][33] padded, 33.8 KB
        float* cred = (float*)(sm + 33792);      // [8][32]
        const int eb = blockIdx.x - MB_TOT;
        const int k0 = eb * 32;

        for (int i = tid; i < D_ * 32; i += 256) {
            int d = i >> 5, kk = i & 31;
            es[d * 33 + kk] = E[(size_t)d * KC + k0 + kk];
        }
        __syncthreads();

        {   // csq: deterministic part-ordered sum of squares per code column.
            const int kk = tid & 31, part = tid >> 5;
            float s = 0.f;
#pragma unroll 8
            for (int dd = 0; dd < 32; ++dd) {
                float v = es[(part * 32 + dd) * 33 + kk];
                s = fmaf(v, v, s);
            }
            cred[part * 32 + kk] = s;
        }
        __syncthreads();
        if (tid < 32) {
            float s = cred[tid];
#pragma unroll
            for (int p = 1; p < 8; ++p) s += cred[p * 32 + tid];
            g_csq[k0 + tid] = s;
        }

        // Code-major fp32 copy E_T[k][d] (for the exact verification pass).
        for (int i = tid; i < 2048; i += 256) {
            int kl = i >> 6, d4 = (i & 63) * 4;
            float4 v;
            v.x = es[(d4 + 0) * 33 + kl];
            v.y = es[(d4 + 1) * 33 + kl];
            v.z = es[(d4 + 2) * 33 + kl];
            v.w = es[(d4 + 3) * 33 + kl];
            *(float4*)&g_ET[(size_t)(k0 + kl) * D_ + d4] = v;
        }

        // Hi B-fragments: [nb][kspair][lane] uint4 = {ks0r0, ks0r1, ks1r0, ks1r1}.
        for (int fi = tid; fi < 1024; fi += 256) {
            int nbl    = fi >> 8;
            int kspair = (fi >> 5) & 7;
            int lane   = fi & 31;
            int gid = lane >> 2, tig = lane & 3;
            int kl  = nbl * 8 + gid;
            uint32_t frag[4];
#pragma unroll
            for (int ksl = 0; ksl < 2; ++ksl)
#pragma unroll
                for (int r = 0; r < 2; ++r) {
                    int d0 = (kspair * 2 + ksl) * 16 + tig * 2 + r * 8;
                    frag[ksl * 2 + r] = pack_h2(__float2half_rn(es[d0 * 33 + kl]),
                                                __float2half_rn(es[(d0 + 1) * 33 + kl]));
                }
            *(uint4*)&g_B[(((size_t)(eb * 4 + nbl) * 8 + kspair) * 32 + lane) * 4] =
                *(uint4*)frag;
        }
    }
}

// ---------------------------------------------------------------------------
// Pass 1: hi*hi MMA only; per-(token, 16-code-group) approx minima to g_gmin.
// A fragments register-prefetched one ksl ahead (ks cycles 0..15).
// ---------------------------------------------------------------------------
__device__ __forceinline__ void loadB(uint4* bnew, int it, int nwarp, int lane) {
    const int ntile = it >> 3, kspair = it & 7;
    const uint4* base = (const uint4*)g_B +
        (((size_t)(ntile * 16 + nwarp * 4) * 8 + kspair) * 32 + lane);
#pragma unroll
    for (int nf = 0; nf < 4; ++nf)
        bnew[nf] = __ldg(base + nf * 256);       // nf stride: 8*32 uint4
}

#define LOAD_A(dst, ksv)                                                      \
    _Pragma("unroll")                                                         \
    for (int mf = 0; mf < 4; ++mf)                                            \
        (dst)[mf] = *(const uint4*)(As + (((mwarp * 4 + mf) * 16 + (ksv)) * 32 + lane) * 4)

#define MMA_ITER(II)                                                          \
    do {                                                                      \
        const int it = it0 + (II);                                            \
        const int ntile = it >> 3, kspair = it & 7;                           \
        uint4 bcur[4];                                                        \
        _Pragma("unroll")                                                     \
        for (int q = 0; q < 4; ++q) bcur[q] = bnxt[q];                        \
        if ((II) + 1 < NITERL) loadB(bnxt, it + 1, nwarp, lane);              \
        if (kspair == 0) {                                                    \
            _Pragma("unroll")                                                 \
            for (int mf = 0; mf < 4; ++mf)                                    \
                _Pragma("unroll")                                             \
                for (int nf = 0; nf < 4; ++nf)                                \
                    _Pragma("unroll")                                         \
                    for (int c = 0; c < 4; ++c) acc[mf][nf][c] = 0.f;         \
            _Pragma("unroll")                                                 \
            for (int nf = 0; nf < 4; ++nf) {                                  \
                int kq = ntile * NT + (nwarp * 4 + nf) * 8 + tig * 2;         \
                cregs[nf][0] = __ldg(&g_csq[kq]);                             \
                cregs[nf][1] = __ldg(&g_csq[kq + 1]);                         \
            }                                                                 \
        }                                                                     \
        _Pragma("unroll")                                                     \
        for (int ksl = 0; ksl < 2; ++ksl) {                                   \
            const int ks = kspair * 2 + ksl;                                  \
            uint4 acur[4];                                                    \
            _Pragma("unroll")                                                 \
            for (int mf = 0; mf < 4; ++mf) acur[mf] = anxt[mf];               \
            LOAD_A(anxt, (ks + 1) & 15);                                      \
            _Pragma("unroll")                                                 \
            for (int mf = 0; mf < 4; ++mf)                                    \
                _Pragma("unroll")                                             \
                for (int nf = 0; nf < 4; ++nf)                                \
                    mma16816(acc[mf][nf], (const uint32_t*)&acur[mf],         \
                             ((const uint32_t*)&bcur[nf]) + ksl * 2);         \
        }                                                                     \
        if (kspair == 7) {                                                    \
            float* sg = sgm + (ntile & 1) * SGM_FLOATS;                       \
            _Pragma("unroll")                                                 \
            for (int mf = 0; mf < 4; ++mf)                                    \
                _Pragma("unroll")                                             \
                for (int hh = 0; hh < 2; ++hh)                                \
                    _Pragma("unroll")                                         \
                    for (int nf = 0; nf < 4; ++nf) {                          \
                        float m0 = fmaf(-2.f, acc[mf][nf][hh * 2],     cregs[nf][0]); \
                        float m1 = fmaf(-2.f, acc[mf][nf][hh * 2 + 1], cregs[nf][1]); \
                        int row = mwarp * 64 + mf * 16 + hh * 8 + gid;        \
                        sg[row * SGM_STRIDE + (nwarp * 4 + nf) * 4 + tig] =   \
                            fminf(m0, m1);                                    \
                    }                                                         \
            __syncthreads();                                                  \
            {                                                                 \
                int r = tid >> 1, c0 = (tid & 1) * 4;                         \
                float o4[4];                                                  \
                _Pragma("unroll")                                             \
                for (int g = 0; g < 4; ++g) {                                 \
                    float4 ta = *(float4*)&sg[r * SGM_STRIDE + (c0 + g) * 8]; \
                    float4 tb = *(float4*)&sg[r * SGM_STRIDE + (c0 + g) * 8 + 4]; \
                    o4[g] = fminf(fminf(fminf(ta.x, ta.y), fminf(ta.z, ta.w)),\
                                  fminf(fminf(tb.x, tb.y), fminf(tb.z, tb.w)));\
                }                                                             \
                *(float4*)&g_gmin[(size_t)(n0 + r) * NGRP + ntile * 8 + c0] = \
                    make_float4(o4[0], o4[1], o4[2], o4[3]);                  \
            }                                                                 \
        }                                                                     \
    } while (0)

__global__ __launch_bounds__(256, 1) void vq_mma_kernel() {
    extern __shared__ char smem[];
    uint32_t* As = (uint32_t*)smem;
    float* sgm = (float*)(smem + SMEM_A_BYTES);
    const uint32_t sA = smem_u32(As);

    const int tid = threadIdx.x;
    const int wid = tid >> 5, lane = tid & 31;
    const int gid = lane >> 2, tig = lane & 3;
    const int mwarp = wid >> 2, nwarp = wid & 3;

    const int bx = blockIdx.x;                // 0..1023
    const int part   = bx & (NPARTS - 1);
    const int tileid = bx >> 3;
    const int mb0 = tileid * 8;
    const int n0  = tileid * MT;
    const int it0 = part * NITERL;

    // B pipeline head first (LDGs in flight during the A prologue).
    uint4 bnxt[4];
    loadB(bnxt, it0, nwarp, lane);

    // A prologue (hi only, 64 KB) in two commit groups: ks 0-7, ks 8-15.
    {
        const uint32_t* srcH = g_Ah + (size_t)mb0 * (KS_TOT * 32 * 4);
#pragma unroll
        for (int half = 0; half < 2; ++half) {
            for (int u = tid; u < 2048; u += 256) {
                int mb = u >> 8, ks = ((u >> 5) & 7) + half * 8, ln = u & 31;
                int unit = (mb * 16 + ks) * 32 + ln;     // 16-byte units
                cpasync16(sA + unit * 16, srcH + unit * 4);
            }
            asm volatile("cp.async.commit_group;" ::: "memory");
        }
    }

    float acc[4][4][4];
    float cregs[4][2];
    uint4 anxt[4];

    asm volatile("cp.async.wait_group 1;" ::: "memory");
    __syncthreads();
    LOAD_A(anxt, 0);
#pragma unroll 1
    for (int ii = 0; ii < 4; ++ii) MMA_ITER(ii);

    asm volatile("cp.async.wait_group 0;" ::: "memory");
    __syncthreads();
    LOAD_A(anxt, 8);      // re-arm (the ks=8 prefetch above preceded arrival)
#pragma unroll 1
    for (int ii = 4; ii < NITERL; ++ii) MMA_ITER(ii);
}

// ---------------------------------------------------------------------------
// Pass 2: exact fp32 verification. One warp per token; lane owns dims
// 8*lane..8*lane+7 so codebook rows load as 2x LDG.128.
// thresh = min(gmin) + g_bt[n]; exact-scan qualifying 16-code groups in
// ascending k; lowest index wins ties.
// ---------------------------------------------------------------------------
__global__ __launch_bounds__(256, 1) void vq_finalize(const float* __restrict__ x) {
    const int tid = threadIdx.x;
    const int wid = tid >> 5, lane = tid & 31;
    const int n = blockIdx.x * 8 + wid;
    const int b = n >> 10, s = n & (S_ - 1);

    float xv[8];
    const float* xb = x + ((size_t)b * D_ + lane * 8) * S_ + s;
#pragma unroll
    for (int j = 0; j < 8; ++j) xv[j] = __ldg(&xb[(size_t)j * S_]);

    const float btok = __ldg(&g_bt[n]);

    const float* gm = g_gmin + (size_t)n * NGRP;
    float gv[16];
    float vmin = 3.402823466e+38f;
#pragma unroll
    for (int i = 0; i < 16; ++i) {
        gv[i] = __ldg(&gm[i * 32 + lane]);
        vmin = fminf(vmin, gv[i]);
    }
#pragma unroll
    for (int off = 16; off; off >>= 1)
        vmin = fminf(vmin, __shfl_xor_sync(0xffffffffu, vmin, off));
    const float thresh = vmin + btok;

    float ebest = 3.402823466e+38f;
    int   eidx  = 0;
#pragma unroll
    for (int i = 0; i < 16; ++i) {
        unsigned mask = __ballot_sync(0xffffffffu, gv[i] <= thresh);
        while (mask) {
            int j = __ffs(mask) - 1; mask &= mask - 1;
            int k0 = (i * 32 + j) * 16;
            for (int c = 0; c < 16; ++c) {
                int k = k0 + c;
                const float4* er = (const float4*)(g_ET + (size_t)k * D_ + lane * 8);
                float4 e0 = __ldg(er);
                float4 e1 = __ldg(er + 1);
                float p = 0.f;
                p = fmaf(xv[0], e0.x, p); p = fmaf(xv[1], e0.y, p);
                p = fmaf(xv[2], e0.z, p); p = fmaf(xv[3], e0.w, p);
                p = fmaf(xv[4], e1.x, p); p = fmaf(xv[5], e1.y, p);
                p = fmaf(xv[6], e1.z, p); p = fmaf(xv[7], e1.w, p);
#pragma unroll
                for (int off = 16; off; off >>= 1)
                    p += __shfl_xor_sync(0xffffffffu, p, off);
                float ed = fmaf(-2.f, p, __ldg(&g_csq[k]));
                if (ed < ebest) { ebest = ed; eidx = k; }
            }
        }
    }
    if (lane == 0) g_ind[n] = eidx;
}

// ---------------------------------------------------------------------------
// Outputs (4 tokens per thread, vectorized): exact fp32 op order for STE.
// ---------------------------------------------------------------------------
__global__ void vq_gather_kernel(const float* __restrict__ x,
                                 const float* __restrict__ E,
                                 float* __restrict__ out) {
    size_t t = (size_t)blockIdx.x * blockDim.x + threadIdx.x;  // D_*NTOK/4
    int n4 = (int)(t & (NTOK / 4 - 1));
    int d  = (int)(t >> 12);
    int n  = n4 * 4;
    int b = n >> 10;
    int s = n & (S_ - 1);
    int i0 = g_ind[n];
    int i1 = g_ind[n + 1];
    int i2 = g_ind[n + 2];
    int i3 = g_ind[n + 3];
    const float* Ed = E + (size_t)d * KC;
    float4 q = make_float4(Ed[i0], Ed[i1], Ed[i2], Ed[i3]);
    size_t xo = ((size_t)b * D_ + d) * S_ + s;
    float4 xv = *(const float4*)&x[xo];
    float4 o1 = make_float4(xv.x + (q.x - xv.x), xv.y + (q.y - xv.y),
                            xv.z + (q.z - xv.z), xv.w + (q.w - xv.w));
    *(float4*)&out[xo]       = o1;
    *(float4*)&out[BDS + xo] = q;
    if (d == 0)
        *(float4*)&out[2 * (size_t)BDS + n] =
            make_float4((float)i0, (float)i1, (float)i2, (float)i3);
}

// ---------------------------------------------------------------------------
extern "C" void kernel_launch(void* const* d_in, const int* in_sizes, int n_in,
                              void* d_out, int out_size) {
    const float* x = (const float*)d_in[0];   // [B, D, H, W] fp32
    const float* E = (const float*)d_in[1];   // [D, K] fp32
    float* out = (float*)d_out;

    cudaFuncSetAttribute(vq_mma_kernel,
                         cudaFuncAttributeMaxDynamicSharedMemorySize, SMEM_MAIN);

    vq_split_xe<<<MB_TOT + KC / 32, 256>>>(x, E);
    vq_mma_kernel<<<(NTOK / MT) * NPARTS, 256, SMEM_MAIN>>>();
    vq_finalize<<<NTOK / 8, 256>>>(x);
    vq_gather_kernel<<<(D_ * NTOK / 4) / 256, 256>>>(x, E, out);
}

// round 16
// speedup vs baseline: 2.1196x; 1.0615x over previous
#include <cuda_runtime.h>
#include <cuda_fp16.h>
#include <cstdint>

// Problem constants
#define B_    16
#define D_    256
#define S_    1024
#define NTOK  16384
#define KC    8192
#define BDS   4194304
#define NGRP  512                 // KC/16 code-groups of 16

#define MB_TOT (NTOK / 16)        // 1024 token blocks of 16
#define KS_TOT (D_ / 16)          // 16 k-steps of 16

// Main kernel tiling (8 warps, 4m x 4n warp microtiles), hi-only MMA
#define MT     128
#define NT     128
#define NPARTS 8
#define NITERL 64                 // 8 tiles x 8 kspairs

// smem: A hi tile only (no staging buffers, no mainloop barriers)
#define SMEM_A_BYTES 65536        // [8 mb][16 ks][32 lane][4] u32
#define SMEM_MAIN SMEM_A_BYTES

// Device scratch (allocations forbidden)
__device__ uint32_t g_Ah[MB_TOT * KS_TOT * 32 * 4];   // 8 MB hi A-fragments
__device__ uint32_t g_B [((KC / 8)) * 8 * 32 * 4];    // 4 MB hi B-fragments
__device__ float    g_ET[KC * D_];                    // 8 MB code-major E (fp32)
__device__ float    g_csq[KC];
__device__ float    g_bt[NTOK];                       // per-token bound
__device__ float    g_gmin[(size_t)NTOK * NGRP];      // 32 MB group minima
__device__ int      g_ind[NTOK];

// ---------------------------- helpers --------------------------------------
__device__ __forceinline__ uint32_t smem_u32(const void* p) {
    uint32_t a;
    asm("{ .reg .u64 t; cvta.to.shared.u64 t, %1; cvt.u32.u64 %0, t; }" : "=r"(a) : "l"(p));
    return a;
}
__device__ __forceinline__ void cpasync16(uint32_t dst, const void* src) {
    asm volatile("cp.async.cg.shared.global [%0], [%1], 16;" :: "r"(dst), "l"(src));
}
__device__ __forceinline__ void mma16816(float* c, const uint32_t* a, const uint32_t* b) {
    asm volatile("mma.sync.aligned.m16n8k16.row.col.f32.f16.f16.f32 "
                 "{%0,%1,%2,%3}, {%4,%5,%6,%7}, {%8,%9}, {%0,%1,%2,%3};"
                 : "+f"(c[0]), "+f"(c[1]), "+f"(c[2]), "+f"(c[3])
                 : "r"(a[0]), "r"(a[1]), "r"(a[2]), "r"(a[3]), "r"(b[0]), "r"(b[1]));
}
__device__ __forceinline__ uint32_t pack_h2(__half lo, __half hi) {
    __half2 h = __halves2half2(lo, hi);
    return *reinterpret_cast<uint32_t*>(&h);
}

// ---------------------------------------------------------------------------
// Fused preprocessing. Blocks [0, MB_TOT): x -> hi A-fragments + btok.
// Blocks [MB_TOT, +KC/32): E -> hi B-fragments + csq + code-major E_T.
// ---------------------------------------------------------------------------
__global__ void vq_split_xe(const float* __restrict__ x,
                            const float* __restrict__ E) {
    __shared__ char sm[36000];
    const int tid = threadIdx.x;

    if (blockIdx.x < MB_TOT) {
        float* xs = (float*)sm;                  // [d][tok] 16 KB
        float* nr = (float*)(sm + 16384);        // [2][16 part][16 tok]
        const int mb = blockIdx.x;
        const int t0 = mb * 16;
        const int b  = t0 >> 10;
        const int s0 = t0 & (S_ - 1);

        for (int i = tid; i < D_ * 16; i += 256) {
            int d = i >> 4, tok = i & 15;
            xs[d * 16 + tok] = x[((size_t)b * D_ + d) * S_ + s0 + tok];
        }
        __syncthreads();

        // Per-token hi/residual norms for the verification bound.
        {
            const int tok = tid & 15, part = tid >> 4;
            float s1 = 0.f, s2 = 0.f;
#pragma unroll
            for (int dd = 0; dd < 16; ++dd) {
                float v = xs[(part * 16 + dd) * 16 + tok];
                float h = __half2float(__float2half_rn(v));
                float r = v - h;
                s1 = fmaf(h, h, s1);
                s2 = fmaf(r, r, s2);
            }
            nr[part * 16 + tok] = s1;
            nr[256 + part * 16 + tok] = s2;
        }
        __syncthreads();
        if (tid < 16) {
            float s1 = 0.f, s2 = 0.f;
#pragma unroll
            for (int p = 0; p < 16; ++p) {
                s1 += nr[p * 16 + tid];
                s2 += nr[256 + p * 16 + tid];
            }
            // Mel = 1.02*2^-11 with ||e|| <= 1.01; Me = 1.01; + eps slack.
            g_bt[t0 + tid] = 2.f * (sqrtf(s1) * 5.0e-4f + sqrtf(s2) * 1.01f) + 0.02f;
        }

        const size_t obase = (size_t)mb * (KS_TOT * 32 * 4);
        for (int oi = tid; oi < KS_TOT * 32 * 4; oi += 256) {
            int ks = oi >> 7, rem = oi & 127;
            int lane = rem >> 2, r = rem & 3;
            int gid = lane >> 2, tig = lane & 3;
            int row = gid + (r & 1) * 8;
            int c0  = ks * 16 + tig * 2 + (r >> 1) * 8;
            float v0 = xs[c0 * 16 + row];
            float v1 = xs[(c0 + 1) * 16 + row];
            g_Ah[obase + oi] = pack_h2(__float2half_rn(v0), __float2half_rn(v1));
        }
    } else {
        float* es   = (float*)sm;                // [256][33] padded, 33.8 KB
        float* cred = (float*)(sm + 33792);      // [8][32]
        const int eb = blockIdx.x - MB_TOT;
        const int k0 = eb * 32;

        for (int i = tid; i < D_ * 32; i += 256) {
            int d = i >> 5, kk = i & 31;
            es[d * 33 + kk] = E[(size_t)d * KC + k0 + kk];
        }
        __syncthreads();

        {   // csq: deterministic part-ordered sum of squares per code column.
            const int kk = tid & 31, part = tid >> 5;
            float s = 0.f;
#pragma unroll 8
            for (int dd = 0; dd < 32; ++dd) {
                float v = es[(part * 32 + dd) * 33 + kk];
                s = fmaf(v, v, s);
            }
            cred[part * 32 + kk] = s;
        }
        __syncthreads();
        if (tid < 32) {
            float s = cred[tid];
#pragma unroll
            for (int p = 1; p < 8; ++p) s += cred[p * 32 + tid];
            g_csq[k0 + tid] = s;
        }

        // Code-major fp32 copy E_T[k][d] (for the exact verification pass).
        for (int i = tid; i < 2048; i += 256) {
            int kl = i >> 6, d4 = (i & 63) * 4;
            float4 v;
            v.x = es[(d4 + 0) * 33 + kl];
            v.y = es[(d4 + 1) * 33 + kl];
            v.z = es[(d4 + 2) * 33 + kl];
            v.w = es[(d4 + 3) * 33 + kl];
            *(float4*)&g_ET[(size_t)(k0 + kl) * D_ + d4] = v;
        }

        // Hi B-fragments: [nb][kspair][lane] uint4 = {ks0r0, ks0r1, ks1r0, ks1r1}.
        for (int fi = tid; fi < 1024; fi += 256) {
            int nbl    = fi >> 8;
            int kspair = (fi >> 5) & 7;
            int lane   = fi & 31;
            int gid = lane >> 2, tig = lane & 3;
            int kl  = nbl * 8 + gid;
            uint32_t frag[4];
#pragma unroll
            for (int ksl = 0; ksl < 2; ++ksl)
#pragma unroll
                for (int r = 0; r < 2; ++r) {
                    int d0 = (kspair * 2 + ksl) * 16 + tig * 2 + r * 8;
                    frag[ksl * 2 + r] = pack_h2(__float2half_rn(es[d0 * 33 + kl]),
                                                __float2half_rn(es[(d0 + 1) * 33 + kl]));
                }
            *(uint4*)&g_B[(((size_t)(eb * 4 + nbl) * 8 + kspair) * 32 + lane) * 4] =
                *(uint4*)frag;
        }
    }
}

// ---------------------------------------------------------------------------
// Pass 1: hi*hi MMA only; per-(token, 16-code-group) minima to g_gmin.
// Epilogue is warp-local (reg fmin + 2 quad-shfl + STG.64): NO mainloop
// barriers. A fragments register-prefetched one ksl ahead.
// ---------------------------------------------------------------------------
__device__ __forceinline__ void loadB(uint4* bnew, int it, int nwarp, int lane) {
    const int ntile = it >> 3, kspair = it & 7;
    const uint4* base = (const uint4*)g_B +
        (((size_t)(ntile * 16 + nwarp * 4) * 8 + kspair) * 32 + lane);
#pragma unroll
    for (int nf = 0; nf < 4; ++nf)
        bnew[nf] = __ldg(base + nf * 256);       // nf stride: 8*32 uint4
}

#define LOAD_A(dst, ksv)                                                      \
    _Pragma("unroll")                                                         \
    for (int mf = 0; mf < 4; ++mf)                                            \
        (dst)[mf] = *(const uint4*)(As + (((mwarp * 4 + mf) * 16 + (ksv)) * 32 + lane) * 4)

#define MMA_ITER(II)                                                          \
    do {                                                                      \
        const int it = it0 + (II);                                            \
        const int ntile = it >> 3, kspair = it & 7;                           \
        uint4 bcur[4];                                                        \
        _Pragma("unroll")                                                     \
        for (int q = 0; q < 4; ++q) bcur[q] = bnxt[q];                        \
        if ((II) + 1 < NITERL) loadB(bnxt, it + 1, nwarp, lane);              \
        if (kspair == 0) {                                                    \
            _Pragma("unroll")                                                 \
            for (int mf = 0; mf < 4; ++mf)                                    \
                _Pragma("unroll")                                             \
                for (int nf = 0; nf < 4; ++nf)                                \
                    _Pragma("unroll")                                         \
                    for (int c = 0; c < 4; ++c) acc[mf][nf][c] = 0.f;         \
            _Pragma("unroll")                                                 \
            for (int nf = 0; nf < 4; ++nf) {                                  \
                int kq = ntile * NT + (nwarp * 4 + nf) * 8 + tig * 2;         \
                cregs[nf][0] = __ldg(&g_csq[kq]);                             \
                cregs[nf][1] = __ldg(&g_csq[kq + 1]);                         \
            }                                                                 \
        }                                                                     \
        _Pragma("unroll")                                                     \
        for (int ksl = 0; ksl < 2; ++ksl) {                                   \
            const int ks = kspair * 2 + ksl;                                  \
            uint4 acur[4];                                                    \
            _Pragma("unroll")                                                 \
            for (int mf = 0; mf < 4; ++mf) acur[mf] = anxt[mf];               \
            LOAD_A(anxt, (ks + 1) & 15);                                      \
            _Pragma("unroll")                                                 \
            for (int mf = 0; mf < 4; ++mf)                                    \
                _Pragma("unroll")                                             \
                for (int nf = 0; nf < 4; ++nf)                                \
                    mma16816(acc[mf][nf], (const uint32_t*)&acur[mf],         \
                             ((const uint32_t*)&bcur[nf]) + ksl * 2);         \
        }                                                                     \
        if (kspair == 7) {                                                    \
            _Pragma("unroll")                                                 \
            for (int mf = 0; mf < 4; ++mf)                                    \
                _Pragma("unroll")                                             \
                for (int hh = 0; hh < 2; ++hh) {                              \
                    float gj[2];                                              \
                    _Pragma("unroll")                                         \
                    for (int j = 0; j < 2; ++j) {                             \
                        float a0 = fmaf(-2.f, acc[mf][2*j  ][hh * 2],     cregs[2*j  ][0]); \
                        float a1 = fmaf(-2.f, acc[mf][2*j  ][hh * 2 + 1], cregs[2*j  ][1]); \
                        float a2 = fmaf(-2.f, acc[mf][2*j+1][hh * 2],     cregs[2*j+1][0]); \
                        float a3 = fmaf(-2.f, acc[mf][2*j+1][hh * 2 + 1], cregs[2*j+1][1]); \
                        float gm = fminf(fminf(a0, a1), fminf(a2, a3));       \
                        gm = fminf(gm, __shfl_xor_sync(0xffffffffu, gm, 1));  \
                        gm = fminf(gm, __shfl_xor_sync(0xffffffffu, gm, 2));  \
                        gj[j] = gm;                                           \
                    }                                                         \
                    if (tig == 0) {                                           \
                        int row = mwarp * 64 + mf * 16 + hh * 8 + gid;        \
                        *(float2*)&g_gmin[(size_t)(n0 + row) * NGRP +         \
                                          ntile * 8 + nwarp * 2] =            \
                            make_float2(gj[0], gj[1]);                        \
                    }                                                         \
                }                                                             \
        }                                                                     \
    } while (0)

__global__ __launch_bounds__(256, 1) void vq_mma_kernel() {
    extern __shared__ char smem[];
    uint32_t* As = (uint32_t*)smem;
    const uint32_t sA = smem_u32(As);

    const int tid = threadIdx.x;
    const int wid = tid >> 5, lane = tid & 31;
    const int gid = lane >> 2, tig = lane & 3;
    const int mwarp = wid >> 2, nwarp = wid & 3;

    const int bx = blockIdx.x;                // 0..1023
    const int part   = bx & (NPARTS - 1);
    const int tileid = bx >> 3;
    const int mb0 = tileid * 8;
    const int n0  = tileid * MT;
    const int it0 = part * NITERL;

    // B pipeline head first (LDGs in flight during the A prologue).
    uint4 bnxt[4];
    loadB(bnxt, it0, nwarp, lane);

    // A prologue (hi only, 64 KB) in two commit groups: ks 0-7, ks 8-15.
    {
        const uint32_t* srcH = g_Ah + (size_t)mb0 * (KS_TOT * 32 * 4);
#pragma unroll
        for (int half = 0; half < 2; ++half) {
            for (int u = tid; u < 2048; u += 256) {
                int mb = u >> 8, ks = ((u >> 5) & 7) + half * 8, ln = u & 31;
                int unit = (mb * 16 + ks) * 32 + ln;     // 16-byte units
                cpasync16(sA + unit * 16, srcH + unit * 4);
            }
            asm volatile("cp.async.commit_group;" ::: "memory");
        }
    }

    float acc[4][4][4];
    float cregs[4][2];
    uint4 anxt[4];

    asm volatile("cp.async.wait_group 1;" ::: "memory");
    __syncthreads();
    LOAD_A(anxt, 0);
#pragma unroll 1
    for (int ii = 0; ii < 4; ++ii) MMA_ITER(ii);

    asm volatile("cp.async.wait_group 0;" ::: "memory");
    __syncthreads();
    LOAD_A(anxt, 8);      // re-arm (the ks=8 prefetch above preceded arrival)
#pragma unroll 1
    for (int ii = 4; ii < NITERL; ++ii) MMA_ITER(ii);
}

// ---------------------------------------------------------------------------
// Pass 2: exact fp32 verification. One warp per token; lane owns dims
// 8*lane..8*lane+7 so codebook rows load as 2x LDG.128.
// thresh = min(gmin) + g_bt[n]; exact-scan qualifying 16-code groups in
// ascending k; lowest index wins ties.
// ---------------------------------------------------------------------------
__global__ __launch_bounds__(256, 1) void vq_finalize(const float* __restrict__ x) {
    const int tid = threadIdx.x;
    const int wid = tid >> 5, lane = tid & 31;
    const int n = blockIdx.x * 8 + wid;
    const int b = n >> 10, s = n & (S_ - 1);

    float xv[8];
    const float* xb = x + ((size_t)b * D_ + lane * 8) * S_ + s;
#pragma unroll
    for (int j = 0; j < 8; ++j) xv[j] = __ldg(&xb[(size_t)j * S_]);

    const float btok = __ldg(&g_bt[n]);

    const float* gm = g_gmin + (size_t)n * NGRP;
    float gv[16];
    float vmin = 3.402823466e+38f;
#pragma unroll
    for (int i = 0; i < 16; ++i) {
        gv[i] = __ldg(&gm[i * 32 + lane]);
        vmin = fminf(vmin, gv[i]);
    }
#pragma unroll
    for (int off = 16; off; off >>= 1)
        vmin = fminf(vmin, __shfl_xor_sync(0xffffffffu, vmin, off));
    const float thresh = vmin + btok;

    float ebest = 3.402823466e+38f;
    int   eidx  = 0;
#pragma unroll
    for (int i = 0; i < 16; ++i) {
        unsigned mask = __ballot_sync(0xffffffffu, gv[i] <= thresh);
        while (mask) {
            int j = __ffs(mask) - 1; mask &= mask - 1;
            int k0 = (i * 32 + j) * 16;
            for (int c = 0; c < 16; ++c) {
                int k = k0 + c;
                const float4* er = (const float4*)(g_ET + (size_t)k * D_ + lane * 8);
                float4 e0 = __ldg(er);
                float4 e1 = __ldg(er + 1);
                float p = 0.f;
                p = fmaf(xv[0], e0.x, p); p = fmaf(xv[1], e0.y, p);
                p = fmaf(xv[2], e0.z, p); p = fmaf(xv[3], e0.w, p);
                p = fmaf(xv[4], e1.x, p); p = fmaf(xv[5], e1.y, p);
                p = fmaf(xv[6], e1.z, p); p = fmaf(xv[7], e1.w, p);
#pragma unroll
                for (int off = 16; off; off >>= 1)
                    p += __shfl_xor_sync(0xffffffffu, p, off);
                float ed = fmaf(-2.f, p, __ldg(&g_csq[k]));
                if (ed < ebest) { ebest = ed; eidx = k; }
            }
        }
    }
    if (lane == 0) g_ind[n] = eidx;
}

// ---------------------------------------------------------------------------
// Outputs (4 tokens per thread, vectorized): exact fp32 op order for STE.
// ---------------------------------------------------------------------------
__global__ void vq_gather_kernel(const float* __restrict__ x,
                                 const float* __restrict__ E,
                                 float* __restrict__ out) {
    size_t t = (size_t)blockIdx.x * blockDim.x + threadIdx.x;  // D_*NTOK/4
    int n4 = (int)(t & (NTOK / 4 - 1));
    int d  = (int)(t >> 12);
    int n  = n4 * 4;
    int b = n >> 10;
    int s = n & (S_ - 1);
    int i0 = g_ind[n];
    int i1 = g_ind[n + 1];
    int i2 = g_ind[n + 2];
    int i3 = g_ind[n + 3];
    const float* Ed = E + (size_t)d * KC;
    float4 q = make_float4(Ed[i0], Ed[i1], Ed[i2], Ed[i3]);
    size_t xo = ((size_t)b * D_ + d) * S_ + s;
    float4 xv = *(const float4*)&x[xo];
    float4 o1 = make_float4(xv.x + (q.x - xv.x), xv.y + (q.y - xv.y),
                            xv.z + (q.z - xv.z), xv.w + (q.w - xv.w));
    *(float4*)&out[xo]       = o1;
    *(float4*)&out[BDS + xo] = q;
    if (d == 0)
        *(float4*)&out[2 * (size_t)BDS + n] =
            make_float4((float)i0, (float)i1, (float)i2, (float)i3);
}

// ---------------------------------------------------------------------------
extern "C" void kernel_launch(void* const* d_in, const int* in_sizes, int n_in,
                              void* d_out, int out_size) {
    const float* x = (const float*)d_in[0];   // [B, D, H, W] fp32
    const float* E = (const float*)d_in[1];   // [D, K] fp32
    float* out = (float*)d_out;

    cudaFuncSetAttribute(vq_mma_kernel,
                         cudaFuncAttributeMaxDynamicSharedMemorySize, SMEM_MAIN);

    vq_split_xe<<<MB_TOT + KC / 32, 256>>>(x, E);
    vq_mma_kernel<<<(NTOK / MT) * NPARTS, 256, SMEM_MAIN>>>();
    vq_finalize<<<NTOK / 8, 256>>>(x);
    vq_gather_kernel<<<(D_ * NTOK / 4) / 256, 256>>>(x, E, out);
}